// round 7
// baseline (speedup 1.0000x reference)
#include <cuda_runtime.h>
#include <cuda_bf16.h>
#include <math.h>
#include <stdint.h>

#define N_NODES 100000
#define N_EDGES 1600000
#define EF 16
#define EH 32
#define NF 128
#define K1 160             // EH + NF
#define TM 64              // nodes per tile
#define NT_TILES ((N_NODES + TM - 1) / TM)   // 1563
#define SA1 162            // bf16 stride of A / W1t rows
#define SH  130            // bf16 stride of H / W2t rows

// ---------------- device scratch (allocation-free) ----------------
__device__ __align__(16) float g_s[(size_t)N_NODES * EF];  // normalized ctx inputs
__device__ __align__(16) int   g_off[N_NODES + 1];         // CSR offsets
__device__ __align__(16) int   g_cur[N_NODES];             // cursors / counts
__device__ __align__(16) uint2 g_pair[N_EDGES];            // {edge id, exp(logit)}
__device__ unsigned int g_ctr;

// ---------------------------------------------------------------------------
// init: zero degree counters, reset tile counter, set CSR sentinel
// ---------------------------------------------------------------------------
#define NCUR4 (N_NODES / 4)     // 25000
__global__ void init_kernel() {
    int i = blockIdx.x * blockDim.x + threadIdx.x;
    if (i == 0) { g_ctr = 0u; g_off[N_NODES] = N_EDGES; }
    if (i < NCUR4) reinterpret_cast<int4*>(g_cur)[i] = make_int4(0, 0, 0, 0);
}

// ---------------------------------------------------------------------------
// hist: degree histogram (integer atomics only)
// ---------------------------------------------------------------------------
__global__ __launch_bounds__(256) void hist_kernel(const int* __restrict__ dst) {
    int e = blockIdx.x * blockDim.x + threadIdx.x;
    atomicAdd(&g_cur[dst[e]], 1);
}

// ---------------------------------------------------------------------------
// scan: single-CTA exclusive prefix over 100k degrees -> g_off, reset g_cur
// ---------------------------------------------------------------------------
#define SCAN_T 1024
#define CHUNK ((N_NODES + SCAN_T - 1) / SCAN_T)   // 98
__global__ __launch_bounds__(SCAN_T) void scan_kernel() {
    __shared__ int sp[SCAN_T];
    int tid = threadIdx.x;
    int lo = tid * CHUNK;
    int hi = lo + CHUNK; if (hi > N_NODES) hi = N_NODES;

    int partial = 0;
    for (int k = lo; k < hi; k++) partial += g_cur[k];

    sp[tid] = partial;
    __syncthreads();
    for (int d = 1; d < SCAN_T; d <<= 1) {
        int v = (tid >= d) ? sp[tid - d] : 0;
        __syncthreads();
        sp[tid] += v;
        __syncthreads();
    }
    int off = sp[tid] - partial;    // exclusive prefix of this chunk

    for (int k = lo; k < hi; k++) {
        int c = g_cur[k];
        g_off[k] = off;
        g_cur[k] = off;             // cursor = start
        off += c;
    }
}

// ---------------------------------------------------------------------------
// scatter: place {eid, exp(logit)} at sorted position (int atomics only)
// ---------------------------------------------------------------------------
__global__ __launch_bounds__(256) void scatter_kernel(
    const float* __restrict__ logits,
    const int*   __restrict__ dst)
{
    int e = blockIdx.x * blockDim.x + threadIdx.x;
    float ex = __expf(logits[e]);
    int d = dst[e];
    int pos = atomicAdd(&g_cur[d], 1);
    g_pair[pos] = make_uint2((unsigned)e, __float_as_uint(ex));
}

// ---------------------------------------------------------------------------
// gather: warp-per-node register reduction; writes NORMALIZED s (no atomics)
// ---------------------------------------------------------------------------
__global__ __launch_bounds__(1024) void gather_kernel(const float* __restrict__ feats)
{
    int wid  = threadIdx.x >> 5;
    int lane = threadIdx.x & 31;
    int n = blockIdx.x * 32 + wid;
    if (n >= N_NODES) return;

    int start = g_off[n];
    int end   = g_off[n + 1];
    int half  = lane >> 4;          // 0/1: alternate edges
    int l0    = lane & 15;          // feature index

    float acc = 0.0f, dacc = 0.0f;
    int i = start + half;
    for (; i + 2 < end; i += 4) {
        uint2 pa = g_pair[i];
        uint2 pb = g_pair[i + 2];
        float exa = __uint_as_float(pa.y);
        float exb = __uint_as_float(pb.y);
        float fa = feats[(size_t)pa.x * EF + l0];
        float fb = feats[(size_t)pb.x * EF + l0];
        acc = fmaf(exa, fa, acc);
        acc = fmaf(exb, fb, acc);
        dacc += exa + exb;
    }
    for (; i < end; i += 2) {
        uint2 p = g_pair[i];
        float ex = __uint_as_float(p.y);
        float f = feats[(size_t)p.x * EF + l0];
        acc = fmaf(ex, f, acc);
        dacc += ex;
    }
    // combine the two halves (lanes 0-15 end with full sums)
    acc  += __shfl_down_sync(0xffffffffu, acc, 16);
    dacc += __shfl_down_sync(0xffffffffu, dacc, 16);

    float inv = (dacc == 0.0f) ? 0.0f : (1.0f / dacc);
    if (lane < 16)
        g_s[(size_t)n * EF + lane] = acc * inv;
}

// ---------------------------------------------------------------------------
// node kernel: split-bf16 tensor-core MLP (mma.sync m16n8k16, 3-pass)
// ---------------------------------------------------------------------------
#define O_W1H 0
#define O_W1L (O_W1H + NF * SA1)
#define O_W2H (O_W1L + NF * SA1)
#define O_W2L (O_W2H + NF * SH)
#define O_AH  (O_W2L + NF * SH)
#define O_AL  (O_AH + TM * SA1)
#define O_HH  (O_AL + TM * SA1)
#define O_HL  (O_HH + TM * SH)
#define O_END (O_HL + TM * SH)
#define O_FLT (O_END * 2)
#define N_FLT (NF + NF + EF * EH + EH)
#define SMEM_BYTES (O_FLT + N_FLT * 4)

#define MMA_BF16(c, a0, a1, a2, a3, b0, b1)                                   \
    asm volatile("mma.sync.aligned.m16n8k16.row.col.f32.bf16.bf16.f32 "       \
                 "{%0,%1,%2,%3}, {%4,%5,%6,%7}, {%8,%9}, {%0,%1,%2,%3};"      \
                 : "+f"((c)[0]), "+f"((c)[1]), "+f"((c)[2]), "+f"((c)[3])     \
                 : "r"(a0), "r"(a1), "r"(a2), "r"(a3), "r"(b0), "r"(b1))

__device__ __forceinline__ uint32_t ld2(const __nv_bfloat16* p) {
    return *reinterpret_cast<const uint32_t*>(p);
}
__device__ __forceinline__ void split2(float v, __nv_bfloat16& h, __nv_bfloat16& l) {
    h = __float2bfloat16(v);
    l = __float2bfloat16(v - __bfloat162float(h));
}
__device__ __forceinline__ uint32_t pack_bf(__nv_bfloat16 a, __nv_bfloat16 b) {
    return (uint32_t)__bfloat16_as_ushort(a)
         | ((uint32_t)__bfloat16_as_ushort(b) << 16);
}

__global__ __launch_bounds__(512, 1) void node_kernel(
    const float* __restrict__ node_feats,
    const float* __restrict__ W_et,
    const float* __restrict__ b_et,
    const float* __restrict__ W1,
    const float* __restrict__ b1,
    const float* __restrict__ W2,
    const float* __restrict__ b2,
    float* __restrict__ out)
{
    __shared__ unsigned s_tile;
    extern __shared__ __align__(16) char smem_raw[];
    __nv_bfloat16* sm   = reinterpret_cast<__nv_bfloat16*>(smem_raw);
    __nv_bfloat16* sW1H = sm + O_W1H;
    __nv_bfloat16* sW1L = sm + O_W1L;
    __nv_bfloat16* sW2H = sm + O_W2H;
    __nv_bfloat16* sW2L = sm + O_W2L;
    __nv_bfloat16* sAH  = sm + O_AH;
    __nv_bfloat16* sAL  = sm + O_AL;
    __nv_bfloat16* sHH  = sm + O_HH;
    __nv_bfloat16* sHL  = sm + O_HL;
    float* sb1  = reinterpret_cast<float*>(smem_raw + O_FLT);
    float* sb2  = sb1 + NF;
    float* sWet = sb2 + NF;
    float* sbet = sWet + EF * EH;

    const int tid  = threadIdx.x;
    const int wid  = tid >> 5;
    const int lane = tid & 31;
    const int gq   = lane >> 2;
    const int tig  = lane & 3;
    const int mi   = wid >> 2;
    const int ni   = wid & 3;

    if (tid == 0) s_tile = atomicAdd(&g_ctr, 1u);
    __syncthreads();
    unsigned tile = s_tile;
    if (tile >= NT_TILES) return;

    for (int i = tid; i < K1 * NF; i += 512) {
        int k = i >> 7, n = i & 127;
        __nv_bfloat16 h, l; split2(W1[i], h, l);
        sW1H[n * SA1 + k] = h;
        sW1L[n * SA1 + k] = l;
    }
    for (int i = tid; i < NF * NF; i += 512) {
        int k = i >> 7, n = i & 127;
        __nv_bfloat16 h, l; split2(W2[i], h, l);
        sW2H[n * SH + k] = h;
        sW2L[n * SH + k] = l;
    }
    if (tid < EF * EH) sWet[tid] = W_et[tid];
    if (tid < EH) sbet[tid] = b_et[tid];
    if (tid < NF) { sb1[tid] = b1[tid]; sb2[tid] = b2[tid]; }
    __syncthreads();

    while (tile < NT_TILES) {
        int base = (int)tile * TM;

        // ---- stage ctx: t already normalized; et = t @ W_et + b_et; elu ----
        {
            int n = tid >> 3;
            int p = tid & 7;
            int node = base + n;
            float t[EF];
            if (node < N_NODES) {
                const float4* sp = reinterpret_cast<const float4*>(g_s + (size_t)node * EF);
                float4 a = sp[0], b = sp[1], c = sp[2], d = sp[3];
                t[0] = a.x;  t[1] = a.y;  t[2] = a.z;  t[3] = a.w;
                t[4] = b.x;  t[5] = b.y;  t[6] = b.z;  t[7] = b.w;
                t[8] = c.x;  t[9] = c.y;  t[10] = c.z; t[11] = c.w;
                t[12] = d.x; t[13] = d.y; t[14] = d.z; t[15] = d.w;
            } else {
#pragma unroll
                for (int k = 0; k < EF; k++) t[k] = 0.0f;
            }
#pragma unroll
            for (int jj = 0; jj < 4; jj++) {
                int jc = p * 4 + jj;
                float acc = sbet[jc];
#pragma unroll
                for (int k = 0; k < EF; k++)
                    acc = fmaf(t[k], sWet[k * EH + jc], acc);
                float v = (acc > 0.0f) ? acc : expm1f(acc);
                if (node >= N_NODES) v = 0.0f;
                __nv_bfloat16 h, l; split2(v, h, l);
                sAH[n * SA1 + jc] = h;
                sAL[n * SA1 + jc] = l;
            }
        }
        for (int i = tid; i < TM * NF; i += 512) {
            int n = i >> 7, f = i & 127;
            int node = base + n;
            float v = (node < N_NODES) ? node_feats[(size_t)node * NF + f] : 0.0f;
            __nv_bfloat16 h, l; split2(v, h, l);
            sAH[n * SA1 + EH + f] = h;
            sAL[n * SA1 + EH + f] = l;
        }
        __syncthreads();

        // ================= GEMM1: [64 x 160] @ [160 x 128] =================
        float acc[4][4];
#pragma unroll
        for (int s = 0; s < 4; s++) {
            int col0 = ni * 32 + s * 8 + tig * 2;
            acc[s][0] = sb1[col0];
            acc[s][1] = sb1[col0 + 1];
            acc[s][2] = acc[s][0];
            acc[s][3] = acc[s][1];
        }
        {
            const __nv_bfloat16* aH = sAH + (mi * 16 + gq) * SA1 + tig * 2;
            const __nv_bfloat16* aL = sAL + (mi * 16 + gq) * SA1 + tig * 2;
            const __nv_bfloat16* bH = sW1H + (ni * 32 + gq) * SA1 + tig * 2;
            const __nv_bfloat16* bL = sW1L + (ni * 32 + gq) * SA1 + tig * 2;
#pragma unroll
            for (int kc = 0; kc < K1 / 16; kc++) {
                int ko = kc * 16;
                uint32_t ah0 = ld2(aH + ko),     ah1 = ld2(aH + ko + 8 * SA1);
                uint32_t ah2 = ld2(aH + ko + 8), ah3 = ld2(aH + ko + 8 * SA1 + 8);
                uint32_t al0 = ld2(aL + ko),     al1 = ld2(aL + ko + 8 * SA1);
                uint32_t al2 = ld2(aL + ko + 8), al3 = ld2(aL + ko + 8 * SA1 + 8);
#pragma unroll
                for (int s = 0; s < 4; s++) {
                    const __nv_bfloat16* bhs = bH + s * 8 * SA1 + ko;
                    const __nv_bfloat16* bls = bL + s * 8 * SA1 + ko;
                    uint32_t b0h = ld2(bhs), b1h = ld2(bhs + 8);
                    uint32_t b0l = ld2(bls), b1l = ld2(bls + 8);
                    MMA_BF16(acc[s], ah0, ah1, ah2, ah3, b0h, b1h);
                    MMA_BF16(acc[s], ah0, ah1, ah2, ah3, b0l, b1l);
                    MMA_BF16(acc[s], al0, al1, al2, al3, b0h, b1h);
                }
            }
        }
        {
            int r0 = mi * 16 + gq, r1 = r0 + 8;
#pragma unroll
            for (int s = 0; s < 4; s++) {
                int col0 = ni * 32 + s * 8 + tig * 2;
                float h0 = fmaxf(acc[s][0], 0.0f), h1 = fmaxf(acc[s][1], 0.0f);
                float h2 = fmaxf(acc[s][2], 0.0f), h3 = fmaxf(acc[s][3], 0.0f);
                __nv_bfloat16 a, b, c, d, e, f, g, h;
                split2(h0, a, b); split2(h1, c, d);
                split2(h2, e, f); split2(h3, g, h);
                *reinterpret_cast<uint32_t*>(sHH + r0 * SH + col0) = pack_bf(a, c);
                *reinterpret_cast<uint32_t*>(sHL + r0 * SH + col0) = pack_bf(b, d);
                *reinterpret_cast<uint32_t*>(sHH + r1 * SH + col0) = pack_bf(e, g);
                *reinterpret_cast<uint32_t*>(sHL + r1 * SH + col0) = pack_bf(f, h);
            }
        }
        __syncthreads();

        // ================= GEMM2: [64 x 128] @ [128 x 128] =================
        float acc2[4][4];
#pragma unroll
        for (int s = 0; s < 4; s++) {
            int col0 = ni * 32 + s * 8 + tig * 2;
            acc2[s][0] = sb2[col0];
            acc2[s][1] = sb2[col0 + 1];
            acc2[s][2] = acc2[s][0];
            acc2[s][3] = acc2[s][1];
        }
        {
            const __nv_bfloat16* aH = sHH + (mi * 16 + gq) * SH + tig * 2;
            const __nv_bfloat16* aL = sHL + (mi * 16 + gq) * SH + tig * 2;
            const __nv_bfloat16* bH = sW2H + (ni * 32 + gq) * SH + tig * 2;
            const __nv_bfloat16* bL = sW2L + (ni * 32 + gq) * SH + tig * 2;
#pragma unroll
            for (int kc = 0; kc < NF / 16; kc++) {
                int ko = kc * 16;
                uint32_t ah0 = ld2(aH + ko),     ah1 = ld2(aH + ko + 8 * SH);
                uint32_t ah2 = ld2(aH + ko + 8), ah3 = ld2(aH + ko + 8 * SH + 8);
                uint32_t al0 = ld2(aL + ko),     al1 = ld2(aL + ko + 8 * SH);
                uint32_t al2 = ld2(aL + ko + 8), al3 = ld2(aL + ko + 8 * SH + 8);
#pragma unroll
                for (int s = 0; s < 4; s++) {
                    const __nv_bfloat16* bhs = bH + s * 8 * SH + ko;
                    const __nv_bfloat16* bls = bL + s * 8 * SH + ko;
                    uint32_t b0h = ld2(bhs), b1h = ld2(bhs + 8);
                    uint32_t b0l = ld2(bls), b1l = ld2(bls + 8);
                    MMA_BF16(acc2[s], ah0, ah1, ah2, ah3, b0h, b1h);
                    MMA_BF16(acc2[s], ah0, ah1, ah2, ah3, b0l, b1l);
                    MMA_BF16(acc2[s], al0, al1, al2, al3, b0h, b1h);
                }
            }
        }
        {
            int n0 = base + mi * 16 + gq;
            int n1 = n0 + 8;
#pragma unroll
            for (int s = 0; s < 4; s++) {
                int col0 = ni * 32 + s * 8 + tig * 2;
                if (n0 < N_NODES) {
                    float2 o;
                    o.x = fmaxf(acc2[s][0], 0.0f);
                    o.y = fmaxf(acc2[s][1], 0.0f);
                    *reinterpret_cast<float2*>(out + (size_t)n0 * NF + col0) = o;
                }
                if (n1 < N_NODES) {
                    float2 o;
                    o.x = fmaxf(acc2[s][2], 0.0f);
                    o.y = fmaxf(acc2[s][3], 0.0f);
                    *reinterpret_cast<float2*>(out + (size_t)n1 * NF + col0) = o;
                }
            }
        }

        if (tid == 0) s_tile = atomicAdd(&g_ctr, 1u);
        __syncthreads();
        tile = s_tile;
    }
}

// ---------------------------------------------------------------------------
extern "C" void kernel_launch(void* const* d_in, const int* in_sizes, int n_in,
                              void* d_out, int out_size)
{
    const float* edge_logits = (const float*)d_in[0];
    const float* edge_feats  = (const float*)d_in[1];
    const float* node_feats  = (const float*)d_in[2];
    const int*   dst         = (const int*)d_in[3];
    const float* W_et        = (const float*)d_in[4];
    const float* b_et        = (const float*)d_in[5];
    const float* W1          = (const float*)d_in[6];
    const float* b1          = (const float*)d_in[7];
    const float* W2          = (const float*)d_in[8];
    const float* b2          = (const float*)d_in[9];
    float* out = (float*)d_out;

    static int configured = 0;
    if (!configured) {
        cudaFuncSetAttribute(node_kernel,
                             cudaFuncAttributeMaxDynamicSharedMemorySize, SMEM_BYTES);
        configured = 1;
    }

    init_kernel<<<(NCUR4 + 255) / 256, 256>>>();
    hist_kernel<<<N_EDGES / 256, 256>>>(dst);
    scan_kernel<<<1, SCAN_T>>>();
    scatter_kernel<<<N_EDGES / 256, 256>>>(edge_logits, dst);
    gather_kernel<<<(N_NODES + 31) / 32, 1024>>>(edge_feats);
    node_kernel<<<152, 512, SMEM_BYTES>>>(node_feats, W_et, b_et,
                                          W1, b1, W2, b2, out);
}